// round 14
// baseline (speedup 1.0000x reference)
#include <cuda_runtime.h>
#include <cuda_bf16.h>
#include <stdint.h>

#define B_SZ 4096
#define G_SZ 16
#define BBD  128
#define RFD  1024

// ---------------- scratch (device globals; no allocation) -------------------
__device__ __align__(16) __nv_bfloat16 sRF_h[B_SZ * RFD], sRF_l[B_SZ * RFD];
__device__ __align__(16) __nv_bfloat16 sW1_h[RFD * RFD], sW1_l[RFD * RFD];     // W_rfrf
__device__ __align__(16) __nv_bfloat16 sW2_h[BBD * RFD], sW2_l[BBD * RFD];     // W_rfbb
__device__ __align__(16) __nv_bfloat16 sW3_h[RFD * BBD], sW3_l[RFD * BBD];     // W_bbrf
__device__ __align__(16) __nv_bfloat16 sW4_h[BBD * BBD], sW4_l[BBD * BBD];     // W_bbbb
__device__ __align__(16) __nv_bfloat16 sBB_h[B_SZ * G_SZ * BBD], sBB_l[B_SZ * G_SZ * BBD];
__device__ __align__(16) __nv_bfloat16 sMn_h[B_SZ * BBD], sMn_l[B_SZ * BBD];
__device__ __align__(16) float g_rf2bb[B_SZ * BBD];

// ---------------- small helpers ---------------------------------------------
__device__ __forceinline__ uint32_t smem_u32(const void* p) {
    uint32_t a;
    asm("{ .reg .u64 t; cvta.to.shared.u64 t, %1; cvt.u32.u64 %0, t; }"
        : "=r"(a) : "l"(p));
    return a;
}
__device__ __forceinline__ uint32_t prmt7632(uint32_t a, uint32_t b) {
    uint32_t r;
    asm("prmt.b32 %0, %1, %2, 0x7632;" : "=r"(r) : "r"(a), "r"(b));
    return r;
}
__device__ __forceinline__ uint32_t cvt_bf16x2(float hi_elem, float lo_elem) {
    // result: high 16 = bf16(hi_elem), low 16 = bf16(lo_elem)
    uint32_t r;
    asm("cvt.rn.bf16x2.f32 %0, %1, %2;" : "=r"(r) : "f"(hi_elem), "f"(lo_elem));
    return r;
}
// mish(x) = x * (s^2+2s)/(s^2+2s+2), s=e^x  (exact algebra for tanh(softplus))
__device__ __forceinline__ float mishf(float x) {
    float s = __expf(fminf(x, 15.0f));
    float t = s * (s + 2.0f);
    float r = x * __fdividef(t, t + 2.0f);
    return (x > 15.0f) ? x : r;
}

__device__ __forceinline__ void ldsm4(uint32_t* r, uint32_t a) {
    asm volatile("ldmatrix.sync.aligned.m8n8.x4.shared.b16 {%0,%1,%2,%3}, [%4];"
                 : "=r"(r[0]), "=r"(r[1]), "=r"(r[2]), "=r"(r[3]) : "r"(a));
}
__device__ __forceinline__ void mma16816(float* d, const uint32_t* a,
                                         uint32_t b0, uint32_t b1) {
    asm volatile(
        "mma.sync.aligned.m16n8k16.row.col.f32.bf16.bf16.f32 "
        "{%0,%1,%2,%3},{%4,%5,%6,%7},{%8,%9},{%0,%1,%2,%3};"
        : "+f"(d[0]), "+f"(d[1]), "+f"(d[2]), "+f"(d[3])
        : "r"(a[0]), "r"(a[1]), "r"(a[2]), "r"(a[3]), "r"(b0), "r"(b1));
}

// ---------------- pre-pass: fp32 -> split bf16 hi/lo -------------------------
// hi = truncate-to-bf16 (top 16 bits), lo = rn(x - hi). Error of split-product
// sum (drop lo*lo, round lo): ~5e-5 relative.
__global__ void conv_kernel(const float4* __restrict__ src, int n4, int sel) {
    __nv_bfloat16 *dh, *dl;
    switch (sel) {
        case 0: dh = sRF_h; dl = sRF_l; break;
        case 1: dh = sW1_h; dl = sW1_l; break;
        case 2: dh = sW2_h; dl = sW2_l; break;
        case 3: dh = sW3_h; dl = sW3_l; break;
        case 4: dh = sW4_h; dl = sW4_l; break;
        default: dh = sBB_h; dl = sBB_l; break;
    }
    int i = blockIdx.x * blockDim.x + threadIdx.x;
    if (i >= n4) return;
    float4 v = src[i];
    uint32_t u0 = __float_as_uint(v.x), u1 = __float_as_uint(v.y);
    uint32_t u2 = __float_as_uint(v.z), u3 = __float_as_uint(v.w);
    uint2 H, L;
    H.x = prmt7632(u0, u1);
    H.y = prmt7632(u2, u3);
    float l0 = v.x - __uint_as_float(u0 & 0xffff0000u);
    float l1 = v.y - __uint_as_float(u1 & 0xffff0000u);
    float l2 = v.z - __uint_as_float(u2 & 0xffff0000u);
    float l3 = v.w - __uint_as_float(u3 & 0xffff0000u);
    L.x = cvt_bf16x2(l1, l0);
    L.y = cvt_bf16x2(l3, l2);
    ((uint2*)dh)[i] = H;
    ((uint2*)dl)[i] = L;
}

// mean over G, then split into sMn_h/l
__global__ void mean_split(const float* __restrict__ BBf) {
    int idx = blockIdx.x * blockDim.x + threadIdx.x;  // 0..B*128-1
    int b = idx >> 7;
    int i = idx & 127;
    const float* p = BBf + (size_t)b * (G_SZ * BBD) + i;
    float s = 0.f;
#pragma unroll
    for (int g = 0; g < G_SZ; g++) s += p[g * BBD];
    float m = s * (1.0f / G_SZ);
    uint32_t bits = __float_as_uint(m);
    float hi = __uint_as_float(bits & 0xffff0000u);
    ((uint16_t*)sMn_h)[idx] = (uint16_t)(bits >> 16);
    sMn_l[idx] = __float2bfloat16(m - hi);
}

// ---------------- GEMM core --------------------------------------------------
// CTA tile 128x128, k-chunk 64, double-buffered cp.async. Both A and W are
// [rows, K] bf16 (K contiguous). SMEM buffer (65536B): Ah@0 Al@16384 Wh@32768
// Wl@49152; each tile 128 rows x 128B, segments xor-swizzled by (row&7).
#define BUF_SZ 65536u

__device__ __forceinline__ void cp_tile(uint32_t dst, const __nv_bfloat16* src,
                                        int ld, int kbase, int tid) {
    int s0 = tid & 7;
    int r0 = tid >> 3;  // 0..31
    uint32_t seg = (uint32_t)((s0 ^ (r0 & 7)) << 4);
#pragma unroll
    for (int p = 0; p < 4; p++) {
        int row = r0 + 32 * p;
        uint32_t d = dst + (uint32_t)row * 128 + seg;
        const void* s = src + (size_t)row * ld + kbase + s0 * 8;
        asm volatile("cp.async.cg.shared.global [%0], [%1], 16;"
                     :: "r"(d), "l"(s) : "memory");
    }
}

__device__ __forceinline__ void cp_chunk(uint32_t buf,
    const __nv_bfloat16* Ah, const __nv_bfloat16* Al, int lda,
    const __nv_bfloat16* Wh, const __nv_bfloat16* Wl, int ldw,
    int kbase, int tid)
{
    cp_tile(buf + 0u,     Ah, lda, kbase, tid);
    cp_tile(buf + 16384u, Al, lda, kbase, tid);
    cp_tile(buf + 32768u, Wh, ldw, kbase, tid);
    cp_tile(buf + 49152u, Wl, ldw, kbase, tid);
    asm volatile("cp.async.commit_group;" ::: "memory");
}

__device__ __forceinline__ void compute_chunk(uint32_t buf, float acc[2][8][4],
                                              int lane, int wm, int wn) {
#pragma unroll
    for (int ks = 0; ks < 4; ks++) {
        uint32_t ah[2][4], al[2][4];
        int arow0 = wm + (lane & 15);
        uint32_t aseg = (uint32_t)(((ks * 2 + (lane >> 4)) ^ (lane & 7)) << 4);
#pragma unroll
        for (int i = 0; i < 2; i++) {
            uint32_t ad = buf + (uint32_t)(arow0 + i * 16) * 128 + aseg;
            ldsm4(ah[i], ad);
            ldsm4(al[i], ad + 16384u);
        }
        int nrow0 = wn + (lane & 7) + ((lane >> 4) & 1) * 8;
        uint32_t bseg = (uint32_t)(((ks * 2 + ((lane >> 3) & 1)) ^ (lane & 7)) << 4);
#pragma unroll
        for (int jj = 0; jj < 4; jj++) {
            uint32_t bh[4], bl[4];
            uint32_t bd = buf + 32768u + (uint32_t)(nrow0 + jj * 16) * 128 + bseg;
            ldsm4(bh, bd);
            ldsm4(bl, bd + 16384u);
            // product-major ordering: 4 independent accs between reuses
#pragma unroll
            for (int i = 0; i < 2; i++) {
                mma16816(acc[i][jj * 2 + 0], ah[i], bh[0], bh[1]);
                mma16816(acc[i][jj * 2 + 1], ah[i], bh[2], bh[3]);
            }
#pragma unroll
            for (int i = 0; i < 2; i++) {
                mma16816(acc[i][jj * 2 + 0], ah[i], bl[0], bl[1]);
                mma16816(acc[i][jj * 2 + 1], ah[i], bl[2], bl[3]);
            }
#pragma unroll
            for (int i = 0; i < 2; i++) {
                mma16816(acc[i][jj * 2 + 0], al[i], bh[0], bh[1]);
                mma16816(acc[i][jj * 2 + 1], al[i], bh[2], bh[3]);
            }
        }
    }
}

__device__ __forceinline__ void gemm_bf16(
    const __nv_bfloat16* __restrict__ Ah, const __nv_bfloat16* __restrict__ Al, int lda,
    const __nv_bfloat16* __restrict__ Wh, const __nv_bfloat16* __restrict__ Wl, int ldw,
    int nc, float acc[2][8][4], uint32_t smu, int tid, int lane, int wm, int wn)
{
    cp_chunk(smu, Ah, Al, lda, Wh, Wl, ldw, 0, tid);
    for (int c = 0; c < nc; c++) {
        if (c + 1 < nc) {
            cp_chunk(smu + ((c + 1) & 1) * BUF_SZ, Ah, Al, lda, Wh, Wl, ldw,
                     (c + 1) * 64, tid);
            asm volatile("cp.async.wait_group 1;" ::: "memory");
        } else {
            asm volatile("cp.async.wait_group 0;" ::: "memory");
        }
        __syncthreads();
        compute_chunk(smu + (c & 1) * BUF_SZ, acc, lane, wm, wn);
        __syncthreads();
    }
}

#define ZERO_ACC(acc) do { \
    _Pragma("unroll") for (int i = 0; i < 2; i++) \
    _Pragma("unroll") for (int j = 0; j < 8; j++) \
    _Pragma("unroll") for (int k = 0; k < 4; k++) acc[i][j][k] = 0.f; } while (0)

// ---------------- fused kernel: new_RF tiles (0..255) + rf2bb tiles (256..287)
__global__ __launch_bounds__(256) void fused_rf(
    const float* __restrict__ brfrf, const float* __restrict__ bbbrf,
    const float* __restrict__ brfbb, float* __restrict__ outRF)
{
    extern __shared__ char sm[];
    uint32_t smu = smem_u32(sm);
    const int tid = threadIdx.x, lane = tid & 31, wid = tid >> 5;
    const int wm = (wid & 3) * 32, wn = (wid >> 2) * 64;
    const int g = lane >> 2, q = (lane & 3) * 2;
    float acc[2][8][4];
    const int bid = blockIdx.x;

    if (bid < 256) {
        const int bm = (bid >> 3) * 128, bn = (bid & 7) * 128;
        ZERO_ACC(acc);
        gemm_bf16(sRF_h + (size_t)bm * RFD, sRF_l + (size_t)bm * RFD, RFD,
                  sW1_h + (size_t)bn * RFD, sW1_l + (size_t)bn * RFD, RFD,
                  16, acc, smu, tid, lane, wm, wn);
        // phase-1 result -> SMEM (beyond the two 64KB buffers)
        float* res = (float*)(sm + 131072);
#pragma unroll
        for (int i = 0; i < 2; i++)
#pragma unroll
            for (int j = 0; j < 8; j++) {
                int r = wm + i * 16 + g;
                int cc = wn + j * 8 + q;
                float b0 = brfrf[bn + cc], b1 = brfrf[bn + cc + 1];
                *(float2*)&res[r * 128 + cc] =
                    make_float2(mishf(acc[i][j][0] + b0), mishf(acc[i][j][1] + b1));
                *(float2*)&res[(r + 8) * 128 + cc] =
                    make_float2(mishf(acc[i][j][2] + b0), mishf(acc[i][j][3] + b1));
            }
        ZERO_ACC(acc);
        gemm_bf16(sMn_h + (size_t)bm * BBD, sMn_l + (size_t)bm * BBD, BBD,
                  sW3_h + (size_t)bn * BBD, sW3_l + (size_t)bn * BBD, BBD,
                  2, acc, smu, tid, lane, wm, wn);
#pragma unroll
        for (int i = 0; i < 2; i++)
#pragma unroll
            for (int j = 0; j < 8; j++) {
                int r = wm + i * 16 + g;
                int cc = wn + j * 8 + q;
                float b0 = bbbrf[bn + cc], b1 = bbbrf[bn + cc + 1];
                float2 p0 = *(float2*)&res[r * 128 + cc];
                float2 p1 = *(float2*)&res[(r + 8) * 128 + cc];
                *(float2*)&outRF[(size_t)(bm + r) * RFD + bn + cc] =
                    make_float2(p0.x + mishf(acc[i][j][0] + b0),
                                p0.y + mishf(acc[i][j][1] + b1));
                *(float2*)&outRF[(size_t)(bm + r + 8) * RFD + bn + cc] =
                    make_float2(p1.x + mishf(acc[i][j][2] + b0),
                                p1.y + mishf(acc[i][j][3] + b1));
            }
    } else {
        const int bm = (bid - 256) * 128;
        ZERO_ACC(acc);
        gemm_bf16(sRF_h + (size_t)bm * RFD, sRF_l + (size_t)bm * RFD, RFD,
                  sW2_h, sW2_l, RFD,
                  16, acc, smu, tid, lane, wm, wn);
#pragma unroll
        for (int i = 0; i < 2; i++)
#pragma unroll
            for (int j = 0; j < 8; j++) {
                int r = wm + i * 16 + g;
                int cc = wn + j * 8 + q;
                float b0 = brfbb[cc], b1 = brfbb[cc + 1];
                *(float2*)&g_rf2bb[(size_t)(bm + r) * BBD + cc] =
                    make_float2(mishf(acc[i][j][0] + b0), mishf(acc[i][j][1] + b1));
                *(float2*)&g_rf2bb[(size_t)(bm + r + 8) * BBD + cc] =
                    make_float2(mishf(acc[i][j][2] + b0), mishf(acc[i][j][3] + b1));
            }
    }
}

// ---------------- new_BB: [65536,128] @ W_bbbb^T + mish + broadcast add ------
__global__ __launch_bounds__(256) void new_bb_k(
    const float* __restrict__ bbbbb, float* __restrict__ outBB)
{
    extern __shared__ char sm[];
    uint32_t smu = smem_u32(sm);
    const int tid = threadIdx.x, lane = tid & 31, wid = tid >> 5;
    const int wm = (wid & 3) * 32, wn = (wid >> 2) * 64;
    const int g = lane >> 2, q = (lane & 3) * 2;
    const int bm = blockIdx.x * 128;
    float acc[2][8][4];
    ZERO_ACC(acc);
    gemm_bf16(sBB_h + (size_t)bm * BBD, sBB_l + (size_t)bm * BBD, BBD,
              sW4_h, sW4_l, BBD,
              2, acc, smu, tid, lane, wm, wn);
#pragma unroll
    for (int i = 0; i < 2; i++)
#pragma unroll
        for (int j = 0; j < 8; j++) {
            int r = wm + i * 16 + g;
            int cc = wn + j * 8 + q;
            float b0 = bbbbb[cc], b1 = bbbbb[cc + 1];
            int m0 = bm + r, m1 = bm + r + 8;
            float2 a0 = *(const float2*)&g_rf2bb[(size_t)(m0 >> 4) * BBD + cc];
            float2 a1 = *(const float2*)&g_rf2bb[(size_t)(m1 >> 4) * BBD + cc];
            *(float2*)&outBB[(size_t)m0 * BBD + cc] =
                make_float2(mishf(acc[i][j][0] + b0) + a0.x,
                            mishf(acc[i][j][1] + b1) + a0.y);
            *(float2*)&outBB[(size_t)m1 * BBD + cc] =
                make_float2(mishf(acc[i][j][2] + b0) + a1.x,
                            mishf(acc[i][j][3] + b1) + a1.y);
        }
}

// ---------------------------------------------------------------------------
extern "C" void kernel_launch(void* const* d_in, const int* in_sizes, int n_in,
                              void* d_out, int out_size)
{
    const float* BBf   = (const float*)d_in[0];  // [4096,16,128]
    const float* RF    = (const float*)d_in[1];  // [4096,1024]
    const float* Wrfbb = (const float*)d_in[2];  // [128,1024]
    const float* brfbb = (const float*)d_in[3];
    const float* Wrfrf = (const float*)d_in[4];  // [1024,1024]
    const float* brfrf = (const float*)d_in[5];
    const float* Wbbrf = (const float*)d_in[6];  // [1024,128]
    const float* bbbrf = (const float*)d_in[7];
    const float* Wbbbb = (const float*)d_in[8];  // [128,128]
    const float* bbbbb = (const float*)d_in[9];

    float* out    = (float*)d_out;
    float* new_BB = out;                              // [4096,16,128]
    float* new_RF = out + (size_t)B_SZ * G_SZ * BBD;  // [4096,1024]

    static int attr_done = 0;
    if (!attr_done) {
        cudaFuncSetAttribute(fused_rf, cudaFuncAttributeMaxDynamicSharedMemorySize,
                             196608);
        cudaFuncSetAttribute(new_bb_k, cudaFuncAttributeMaxDynamicSharedMemorySize,
                             131072);
        attr_done = 1;
    }

    // pre-pass conversions (each element exactly once)
    conv_kernel<<<(B_SZ * RFD / 4) / 256, 256>>>((const float4*)RF,    B_SZ * RFD / 4, 0);
    conv_kernel<<<(RFD * RFD / 4) / 256, 256>>>((const float4*)Wrfrf,  RFD * RFD / 4, 1);
    conv_kernel<<<(BBD * RFD / 4) / 256, 256>>>((const float4*)Wrfbb,  BBD * RFD / 4, 2);
    conv_kernel<<<(RFD * BBD / 4) / 256, 256>>>((const float4*)Wbbrf,  RFD * BBD / 4, 3);
    conv_kernel<<<(BBD * BBD / 4) / 256, 256>>>((const float4*)Wbbbb,  BBD * BBD / 4, 4);
    conv_kernel<<<(B_SZ * G_SZ * BBD / 4) / 256, 256>>>((const float4*)BBf,
                                                        B_SZ * G_SZ * BBD / 4, 5);
    mean_split<<<(B_SZ * BBD) / 256, 256>>>(BBf);

    // new_RF (256 tiles) + rf2bb (32 tiles) in one grid
    fused_rf<<<288, 256, 196608>>>(brfrf, bbbrf, brfbb, new_RF);
    // new_BB
    new_bb_k<<<512, 256, 131072>>>(bbbbb, new_BB);
}

// round 15
// speedup vs baseline: 1.0021x; 1.0021x over previous
#include <cuda_runtime.h>
#include <cuda_bf16.h>
#include <stdint.h>

#define B_SZ 4096
#define G_SZ 16
#define BBD  128
#define RFD  1024

// ---------------- scratch (device globals; no allocation) -------------------
__device__ __align__(16) __nv_bfloat16 sRF_h[B_SZ * RFD], sRF_l[B_SZ * RFD];
__device__ __align__(16) __nv_bfloat16 sW1_h[RFD * RFD], sW1_l[RFD * RFD];     // W_rfrf
__device__ __align__(16) __nv_bfloat16 sW2_h[BBD * RFD], sW2_l[BBD * RFD];     // W_rfbb
__device__ __align__(16) __nv_bfloat16 sW3_h[RFD * BBD], sW3_l[RFD * BBD];     // W_bbrf
__device__ __align__(16) __nv_bfloat16 sW4_h[BBD * BBD], sW4_l[BBD * BBD];     // W_bbbb
__device__ __align__(16) __nv_bfloat16 sBB_h[B_SZ * G_SZ * BBD], sBB_l[B_SZ * G_SZ * BBD];
__device__ __align__(16) __nv_bfloat16 sMn_h[B_SZ * BBD], sMn_l[B_SZ * BBD];
__device__ __align__(16) float g_rf2bb[B_SZ * BBD];

// ---------------- small helpers ---------------------------------------------
__device__ __forceinline__ uint32_t smem_u32(const void* p) {
    uint32_t a;
    asm("{ .reg .u64 t; cvta.to.shared.u64 t, %1; cvt.u32.u64 %0, t; }"
        : "=r"(a) : "l"(p));
    return a;
}
__device__ __forceinline__ uint32_t prmt7632(uint32_t a, uint32_t b) {
    uint32_t r;
    asm("prmt.b32 %0, %1, %2, 0x7632;" : "=r"(r) : "r"(a), "r"(b));
    return r;
}
__device__ __forceinline__ uint32_t cvt_bf16x2(float hi_elem, float lo_elem) {
    // result: high 16 = bf16(hi_elem), low 16 = bf16(lo_elem)
    uint32_t r;
    asm("cvt.rn.bf16x2.f32 %0, %1, %2;" : "=r"(r) : "f"(hi_elem), "f"(lo_elem));
    return r;
}
// mish(x) = x * (s^2+2s)/(s^2+2s+2), s=e^x  (exact algebra for tanh(softplus))
__device__ __forceinline__ float mishf(float x) {
    float s = __expf(fminf(x, 15.0f));
    float t = s * (s + 2.0f);
    float r = x * __fdividef(t, t + 2.0f);
    return (x > 15.0f) ? x : r;
}

__device__ __forceinline__ void ldsm4(uint32_t* r, uint32_t a) {
    asm volatile("ldmatrix.sync.aligned.m8n8.x4.shared.b16 {%0,%1,%2,%3}, [%4];"
                 : "=r"(r[0]), "=r"(r[1]), "=r"(r[2]), "=r"(r[3]) : "r"(a));
}
__device__ __forceinline__ void mma16816(float* d, const uint32_t* a,
                                         uint32_t b0, uint32_t b1) {
    asm volatile(
        "mma.sync.aligned.m16n8k16.row.col.f32.bf16.bf16.f32 "
        "{%0,%1,%2,%3},{%4,%5,%6,%7},{%8,%9},{%0,%1,%2,%3};"
        : "+f"(d[0]), "+f"(d[1]), "+f"(d[2]), "+f"(d[3])
        : "r"(a[0]), "r"(a[1]), "r"(a[2]), "r"(a[3]), "r"(b0), "r"(b1));
}

// ---------------- pre-pass: fp32 -> split bf16 hi/lo -------------------------
// hi = truncate-to-bf16 (top 16 bits), lo = rn(x - hi). Error of split-product
// sum (drop lo*lo, round lo): ~5e-5 relative.
__global__ void conv_kernel(const float4* __restrict__ src, int n4, int sel) {
    __nv_bfloat16 *dh, *dl;
    switch (sel) {
        case 0: dh = sRF_h; dl = sRF_l; break;
        case 1: dh = sW1_h; dl = sW1_l; break;
        case 2: dh = sW2_h; dl = sW2_l; break;
        case 3: dh = sW3_h; dl = sW3_l; break;
        case 4: dh = sW4_h; dl = sW4_l; break;
        default: dh = sBB_h; dl = sBB_l; break;
    }
    int i = blockIdx.x * blockDim.x + threadIdx.x;
    if (i >= n4) return;
    float4 v = src[i];
    uint32_t u0 = __float_as_uint(v.x), u1 = __float_as_uint(v.y);
    uint32_t u2 = __float_as_uint(v.z), u3 = __float_as_uint(v.w);
    uint2 H, L;
    H.x = prmt7632(u0, u1);
    H.y = prmt7632(u2, u3);
    float l0 = v.x - __uint_as_float(u0 & 0xffff0000u);
    float l1 = v.y - __uint_as_float(u1 & 0xffff0000u);
    float l2 = v.z - __uint_as_float(u2 & 0xffff0000u);
    float l3 = v.w - __uint_as_float(u3 & 0xffff0000u);
    L.x = cvt_bf16x2(l1, l0);
    L.y = cvt_bf16x2(l3, l2);
    ((uint2*)dh)[i] = H;
    ((uint2*)dl)[i] = L;
}

// mean over G, then split into sMn_h/l
__global__ void mean_split(const float* __restrict__ BBf) {
    int idx = blockIdx.x * blockDim.x + threadIdx.x;  // 0..B*128-1
    int b = idx >> 7;
    int i = idx & 127;
    const float* p = BBf + (size_t)b * (G_SZ * BBD) + i;
    float s = 0.f;
#pragma unroll
    for (int g = 0; g < G_SZ; g++) s += p[g * BBD];
    float m = s * (1.0f / G_SZ);
    uint32_t bits = __float_as_uint(m);
    float hi = __uint_as_float(bits & 0xffff0000u);
    ((uint16_t*)sMn_h)[idx] = (uint16_t)(bits >> 16);
    sMn_l[idx] = __float2bfloat16(m - hi);
}

// ---------------- GEMM core --------------------------------------------------
// CTA tile 128x128, k-chunk 64, double-buffered cp.async. Both A and W are
// [rows, K] bf16 (K contiguous). SMEM buffer (65536B): Ah@0 Al@16384 Wh@32768
// Wl@49152; each tile 128 rows x 128B, segments xor-swizzled by (row&7).
#define BUF_SZ 65536u

__device__ __forceinline__ void cp_tile(uint32_t dst, const __nv_bfloat16* src,
                                        int ld, int kbase, int tid) {
    int s0 = tid & 7;
    int r0 = tid >> 3;  // 0..31
    uint32_t seg = (uint32_t)((s0 ^ (r0 & 7)) << 4);
#pragma unroll
    for (int p = 0; p < 4; p++) {
        int row = r0 + 32 * p;
        uint32_t d = dst + (uint32_t)row * 128 + seg;
        const void* s = src + (size_t)row * ld + kbase + s0 * 8;
        asm volatile("cp.async.cg.shared.global [%0], [%1], 16;"
                     :: "r"(d), "l"(s) : "memory");
    }
}

__device__ __forceinline__ void cp_chunk(uint32_t buf,
    const __nv_bfloat16* Ah, const __nv_bfloat16* Al, int lda,
    const __nv_bfloat16* Wh, const __nv_bfloat16* Wl, int ldw,
    int kbase, int tid)
{
    cp_tile(buf + 0u,     Ah, lda, kbase, tid);
    cp_tile(buf + 16384u, Al, lda, kbase, tid);
    cp_tile(buf + 32768u, Wh, ldw, kbase, tid);
    cp_tile(buf + 49152u, Wl, ldw, kbase, tid);
    asm volatile("cp.async.commit_group;" ::: "memory");
}

__device__ __forceinline__ void compute_chunk(uint32_t buf, float acc[2][8][4],
                                              int lane, int wm, int wn) {
#pragma unroll
    for (int ks = 0; ks < 4; ks++) {
        uint32_t ah[2][4], al[2][4];
        int arow0 = wm + (lane & 15);
        uint32_t aseg = (uint32_t)(((ks * 2 + (lane >> 4)) ^ (lane & 7)) << 4);
#pragma unroll
        for (int i = 0; i < 2; i++) {
            uint32_t ad = buf + (uint32_t)(arow0 + i * 16) * 128 + aseg;
            ldsm4(ah[i], ad);
            ldsm4(al[i], ad + 16384u);
        }
        int nrow0 = wn + (lane & 7) + ((lane >> 4) & 1) * 8;
        uint32_t bseg = (uint32_t)(((ks * 2 + ((lane >> 3) & 1)) ^ (lane & 7)) << 4);
#pragma unroll
        for (int jj = 0; jj < 4; jj++) {
            uint32_t bh[4], bl[4];
            uint32_t bd = buf + 32768u + (uint32_t)(nrow0 + jj * 16) * 128 + bseg;
            ldsm4(bh, bd);
            ldsm4(bl, bd + 16384u);
            // product-major ordering: 4 independent accs between reuses
#pragma unroll
            for (int i = 0; i < 2; i++) {
                mma16816(acc[i][jj * 2 + 0], ah[i], bh[0], bh[1]);
                mma16816(acc[i][jj * 2 + 1], ah[i], bh[2], bh[3]);
            }
#pragma unroll
            for (int i = 0; i < 2; i++) {
                mma16816(acc[i][jj * 2 + 0], ah[i], bl[0], bl[1]);
                mma16816(acc[i][jj * 2 + 1], ah[i], bl[2], bl[3]);
            }
#pragma unroll
            for (int i = 0; i < 2; i++) {
                mma16816(acc[i][jj * 2 + 0], al[i], bh[0], bh[1]);
                mma16816(acc[i][jj * 2 + 1], al[i], bh[2], bh[3]);
            }
        }
    }
}

__device__ __forceinline__ void gemm_bf16(
    const __nv_bfloat16* __restrict__ Ah, const __nv_bfloat16* __restrict__ Al, int lda,
    const __nv_bfloat16* __restrict__ Wh, const __nv_bfloat16* __restrict__ Wl, int ldw,
    int nc, float acc[2][8][4], uint32_t smu, int tid, int lane, int wm, int wn)
{
    cp_chunk(smu, Ah, Al, lda, Wh, Wl, ldw, 0, tid);
    for (int c = 0; c < nc; c++) {
        if (c + 1 < nc) {
            cp_chunk(smu + ((c + 1) & 1) * BUF_SZ, Ah, Al, lda, Wh, Wl, ldw,
                     (c + 1) * 64, tid);
            asm volatile("cp.async.wait_group 1;" ::: "memory");
        } else {
            asm volatile("cp.async.wait_group 0;" ::: "memory");
        }
        __syncthreads();
        compute_chunk(smu + (c & 1) * BUF_SZ, acc, lane, wm, wn);
        __syncthreads();
    }
}

#define ZERO_ACC(acc) do { \
    _Pragma("unroll") for (int i = 0; i < 2; i++) \
    _Pragma("unroll") for (int j = 0; j < 8; j++) \
    _Pragma("unroll") for (int k = 0; k < 4; k++) acc[i][j][k] = 0.f; } while (0)

// ---------------- fused kernel: new_RF tiles (0..255) + rf2bb tiles (256..287)
__global__ __launch_bounds__(256) void fused_rf(
    const float* __restrict__ brfrf, const float* __restrict__ bbbrf,
    const float* __restrict__ brfbb, float* __restrict__ outRF)
{
    extern __shared__ char sm[];
    uint32_t smu = smem_u32(sm);
    const int tid = threadIdx.x, lane = tid & 31, wid = tid >> 5;
    const int wm = (wid & 3) * 32, wn = (wid >> 2) * 64;
    const int g = lane >> 2, q = (lane & 3) * 2;
    float acc[2][8][4];
    const int bid = blockIdx.x;

    if (bid < 256) {
        const int bm = (bid >> 3) * 128, bn = (bid & 7) * 128;
        ZERO_ACC(acc);
        gemm_bf16(sRF_h + (size_t)bm * RFD, sRF_l + (size_t)bm * RFD, RFD,
                  sW1_h + (size_t)bn * RFD, sW1_l + (size_t)bn * RFD, RFD,
                  16, acc, smu, tid, lane, wm, wn);
        // phase-1 result -> SMEM (beyond the two 64KB buffers)
        float* res = (float*)(sm + 131072);
#pragma unroll
        for (int i = 0; i < 2; i++)
#pragma unroll
            for (int j = 0; j < 8; j++) {
                int r = wm + i * 16 + g;
                int cc = wn + j * 8 + q;
                float b0 = brfrf[bn + cc], b1 = brfrf[bn + cc + 1];
                *(float2*)&res[r * 128 + cc] =
                    make_float2(mishf(acc[i][j][0] + b0), mishf(acc[i][j][1] + b1));
                *(float2*)&res[(r + 8) * 128 + cc] =
                    make_float2(mishf(acc[i][j][2] + b0), mishf(acc[i][j][3] + b1));
            }
        ZERO_ACC(acc);
        gemm_bf16(sMn_h + (size_t)bm * BBD, sMn_l + (size_t)bm * BBD, BBD,
                  sW3_h + (size_t)bn * BBD, sW3_l + (size_t)bn * BBD, BBD,
                  2, acc, smu, tid, lane, wm, wn);
#pragma unroll
        for (int i = 0; i < 2; i++)
#pragma unroll
            for (int j = 0; j < 8; j++) {
                int r = wm + i * 16 + g;
                int cc = wn + j * 8 + q;
                float b0 = bbbrf[bn + cc], b1 = bbbrf[bn + cc + 1];
                float2 p0 = *(float2*)&res[r * 128 + cc];
                float2 p1 = *(float2*)&res[(r + 8) * 128 + cc];
                *(float2*)&outRF[(size_t)(bm + r) * RFD + bn + cc] =
                    make_float2(p0.x + mishf(acc[i][j][0] + b0),
                                p0.y + mishf(acc[i][j][1] + b1));
                *(float2*)&outRF[(size_t)(bm + r + 8) * RFD + bn + cc] =
                    make_float2(p1.x + mishf(acc[i][j][2] + b0),
                                p1.y + mishf(acc[i][j][3] + b1));
            }
    } else {
        const int bm = (bid - 256) * 128;
        ZERO_ACC(acc);
        gemm_bf16(sRF_h + (size_t)bm * RFD, sRF_l + (size_t)bm * RFD, RFD,
                  sW2_h, sW2_l, RFD,
                  16, acc, smu, tid, lane, wm, wn);
#pragma unroll
        for (int i = 0; i < 2; i++)
#pragma unroll
            for (int j = 0; j < 8; j++) {
                int r = wm + i * 16 + g;
                int cc = wn + j * 8 + q;
                float b0 = brfbb[cc], b1 = brfbb[cc + 1];
                *(float2*)&g_rf2bb[(size_t)(bm + r) * BBD + cc] =
                    make_float2(mishf(acc[i][j][0] + b0), mishf(acc[i][j][1] + b1));
                *(float2*)&g_rf2bb[(size_t)(bm + r + 8) * BBD + cc] =
                    make_float2(mishf(acc[i][j][2] + b0), mishf(acc[i][j][3] + b1));
            }
    }
}

// ---------------- new_BB: [65536,128] @ W_bbbb^T + mish + broadcast add ------
__global__ __launch_bounds__(256) void new_bb_k(
    const float* __restrict__ bbbbb, float* __restrict__ outBB)
{
    extern __shared__ char sm[];
    uint32_t smu = smem_u32(sm);
    const int tid = threadIdx.x, lane = tid & 31, wid = tid >> 5;
    const int wm = (wid & 3) * 32, wn = (wid >> 2) * 64;
    const int g = lane >> 2, q = (lane & 3) * 2;
    const int bm = blockIdx.x * 128;
    float acc[2][8][4];
    ZERO_ACC(acc);
    gemm_bf16(sBB_h + (size_t)bm * BBD, sBB_l + (size_t)bm * BBD, BBD,
              sW4_h, sW4_l, BBD,
              2, acc, smu, tid, lane, wm, wn);
#pragma unroll
    for (int i = 0; i < 2; i++)
#pragma unroll
        for (int j = 0; j < 8; j++) {
            int r = wm + i * 16 + g;
            int cc = wn + j * 8 + q;
            float b0 = bbbbb[cc], b1 = bbbbb[cc + 1];
            int m0 = bm + r, m1 = bm + r + 8;
            float2 a0 = *(const float2*)&g_rf2bb[(size_t)(m0 >> 4) * BBD + cc];
            float2 a1 = *(const float2*)&g_rf2bb[(size_t)(m1 >> 4) * BBD + cc];
            *(float2*)&outBB[(size_t)m0 * BBD + cc] =
                make_float2(mishf(acc[i][j][0] + b0) + a0.x,
                            mishf(acc[i][j][1] + b1) + a0.y);
            *(float2*)&outBB[(size_t)m1 * BBD + cc] =
                make_float2(mishf(acc[i][j][2] + b0) + a1.x,
                            mishf(acc[i][j][3] + b1) + a1.y);
        }
}

// ---------------------------------------------------------------------------
extern "C" void kernel_launch(void* const* d_in, const int* in_sizes, int n_in,
                              void* d_out, int out_size)
{
    const float* BBf   = (const float*)d_in[0];  // [4096,16,128]
    const float* RF    = (const float*)d_in[1];  // [4096,1024]
    const float* Wrfbb = (const float*)d_in[2];  // [128,1024]
    const float* brfbb = (const float*)d_in[3];
    const float* Wrfrf = (const float*)d_in[4];  // [1024,1024]
    const float* brfrf = (const float*)d_in[5];
    const float* Wbbrf = (const float*)d_in[6];  // [1024,128]
    const float* bbbrf = (const float*)d_in[7];
    const float* Wbbbb = (const float*)d_in[8];  // [128,128]
    const float* bbbbb = (const float*)d_in[9];

    float* out    = (float*)d_out;
    float* new_BB = out;                              // [4096,16,128]
    float* new_RF = out + (size_t)B_SZ * G_SZ * BBD;  // [4096,1024]

    static int attr_done = 0;
    if (!attr_done) {
        cudaFuncSetAttribute(fused_rf, cudaFuncAttributeMaxDynamicSharedMemorySize,
                             196608);
        cudaFuncSetAttribute(new_bb_k, cudaFuncAttributeMaxDynamicSharedMemorySize,
                             131072);
        attr_done = 1;
    }

    // pre-pass conversions (each element exactly once)
    conv_kernel<<<(B_SZ * RFD / 4) / 256, 256>>>((const float4*)RF,    B_SZ * RFD / 4, 0);
    conv_kernel<<<(RFD * RFD / 4) / 256, 256>>>((const float4*)Wrfrf,  RFD * RFD / 4, 1);
    conv_kernel<<<(BBD * RFD / 4) / 256, 256>>>((const float4*)Wrfbb,  BBD * RFD / 4, 2);
    conv_kernel<<<(RFD * BBD / 4) / 256, 256>>>((const float4*)Wbbrf,  RFD * BBD / 4, 3);
    conv_kernel<<<(BBD * BBD / 4) / 256, 256>>>((const float4*)Wbbbb,  BBD * BBD / 4, 4);
    conv_kernel<<<(B_SZ * G_SZ * BBD / 4) / 256, 256>>>((const float4*)BBf,
                                                        B_SZ * G_SZ * BBD / 4, 5);
    mean_split<<<(B_SZ * BBD) / 256, 256>>>(BBf);

    // new_RF (256 tiles) + rf2bb (32 tiles) in one grid
    fused_rf<<<288, 256, 196608>>>(brfrf, bbbrf, brfbb, new_RF);
    // new_BB
    new_bb_k<<<512, 256, 131072>>>(bbbbb, new_BB);
}